// round 15
// baseline (speedup 1.0000x reference)
#include <cuda_runtime.h>
#include <math.h>
#include <stdint.h>

#define BATCH 8
#define DIMC 384
#define HEADS 6
#define HD 64
#define HIN 56
#define LQ 3136        // 56*56
#define LKV 784        // 28*28
#define EPS 1e-5f
#define SCALE 0.05103103630798288f   // 384^-0.5

// ---------------- scratch ----------------
__device__ float g_qc[BATCH * LQ  * DIMC];
__device__ float g_kc[BATCH * LKV * DIMC];
__device__ float g_vc[BATCH * LKV * DIMC];
__device__ float g_qp[BATCH * LQ  * DIMC];
__device__ float g_kp[BATCH * LKV * DIMC];
__device__ float g_vp[BATCH * LKV * DIMC];
__device__ float g_ob[BATCH * LQ  * DIMC];

// ---------------- tf32 helpers ----------------
__device__ __forceinline__ uint32_t f2tf(float f) {
    uint32_t u;
    asm("cvt.rna.tf32.f32 %0, %1;" : "=r"(u) : "f"(f));
    return u;
}

__device__ __forceinline__ void mma_tf32(float c[4], const uint32_t a[4], uint32_t b0, uint32_t b1) {
    asm volatile(
        "mma.sync.aligned.m16n8k8.row.col.f32.tf32.tf32.f32 "
        "{%0,%1,%2,%3}, {%4,%5,%6,%7}, {%8,%9}, {%0,%1,%2,%3};\n"
        : "+f"(c[0]), "+f"(c[1]), "+f"(c[2]), "+f"(c[3])
        : "r"(a[0]), "r"(a[1]), "r"(a[2]), "r"(a[3]), "r"(b0), "r"(b1));
}

// ---------------- depthwise 3x3 conv + BN, float4 channels (q path, stride 1) ----------------
__global__ void dwconv_bn_v4_kernel(const float* __restrict__ x,
                                    const float* __restrict__ wt,
                                    const float* __restrict__ sc,
                                    const float* __restrict__ bb,
                                    const float* __restrict__ mn,
                                    const float* __restrict__ vr,
                                    float* __restrict__ out)
{
    int idx = blockIdx.x * blockDim.x + threadIdx.x;
    const int C4 = DIMC / 4;
    int total = BATCH * LQ * C4;
    if (idx >= total) return;
    int c4 = (idx % C4) * 4;
    int t  = (idx / C4) % LQ;
    int b  = idx / (C4 * LQ);
    int oy = t / HIN, ox = t % HIN;

    float acc[4] = {0.f, 0.f, 0.f, 0.f};
#pragma unroll
    for (int dy = 0; dy < 3; dy++) {
        int iy = oy + dy - 1;
        if (iy < 0 || iy >= HIN) continue;
#pragma unroll
        for (int dx = 0; dx < 3; dx++) {
            int ix = ox + dx - 1;
            if (ix < 0 || ix >= HIN) continue;
            float4 xv = *(const float4*)&x[((size_t)b * LQ + iy * HIN + ix) * DIMC + c4];
            int tap = dy * 3 + dx;
            acc[0] += xv.x * wt[(c4 + 0) * 9 + tap];
            acc[1] += xv.y * wt[(c4 + 1) * 9 + tap];
            acc[2] += xv.z * wt[(c4 + 2) * 9 + tap];
            acc[3] += xv.w * wt[(c4 + 3) * 9 + tap];
        }
    }
    float4 o;
    float* op = &o.x;
#pragma unroll
    for (int j = 0; j < 4; j++) {
        int c = c4 + j;
        float inv = rsqrtf(vr[c] + EPS);
        op[j] = (acc[j] - mn[c]) * inv * sc[c] + bb[c];
    }
    *(float4*)&out[((size_t)b * LQ + t) * DIMC + c4] = o;
}

// ---------------- fused k+v depthwise conv + BN, float4 channels (stride 2) ----------------
__global__ void dwconv_bn_kv_v4_kernel(const float* __restrict__ x,
                                       const float* __restrict__ wtk,
                                       const float* __restrict__ sck,
                                       const float* __restrict__ bbk,
                                       const float* __restrict__ mnk,
                                       const float* __restrict__ vrk,
                                       const float* __restrict__ wtv,
                                       const float* __restrict__ scv,
                                       const float* __restrict__ bbv,
                                       const float* __restrict__ mnv,
                                       const float* __restrict__ vrv,
                                       float* __restrict__ outk,
                                       float* __restrict__ outv)
{
    int idx = blockIdx.x * blockDim.x + threadIdx.x;
    const int C4 = DIMC / 4;
    int total = BATCH * LKV * C4;
    if (idx >= total) return;
    int c4 = (idx % C4) * 4;
    int t  = (idx / C4) % LKV;
    int b  = idx / (C4 * LKV);
    int oy = t / 28, ox = t % 28;

    float ak[4] = {0.f, 0.f, 0.f, 0.f};
    float av[4] = {0.f, 0.f, 0.f, 0.f};
#pragma unroll
    for (int dy = 0; dy < 3; dy++) {
        int iy = oy * 2 + dy - 1;
        if (iy < 0 || iy >= HIN) continue;
#pragma unroll
        for (int dx = 0; dx < 3; dx++) {
            int ix = ox * 2 + dx - 1;
            if (ix < 0 || ix >= HIN) continue;
            float4 xv = *(const float4*)&x[((size_t)b * LQ + iy * HIN + ix) * DIMC + c4];
            int tap = dy * 3 + dx;
            const float* xp = &xv.x;
#pragma unroll
            for (int j = 0; j < 4; j++) {
                ak[j] += xp[j] * wtk[(c4 + j) * 9 + tap];
                av[j] += xp[j] * wtv[(c4 + j) * 9 + tap];
            }
        }
    }
    float4 ok, ov;
    float* okp = &ok.x;
    float* ovp = &ov.x;
#pragma unroll
    for (int j = 0; j < 4; j++) {
        int c = c4 + j;
        okp[j] = (ak[j] - mnk[c]) * rsqrtf(vrk[c] + EPS) * sck[c] + bbk[c];
        ovp[j] = (av[j] - mnv[c]) * rsqrtf(vrv[c] + EPS) * scv[c] + bbv[c];
    }
    size_t off = ((size_t)b * LKV + t) * DIMC + c4;
    *(float4*)&outk[off] = ok;
    *(float4*)&outv[off] = ov;
}

// ---------------- tf32 GEMM body (R11/R12 proven): Y = X @ W^T (+bias) ----------------
#define RSTR 40
#define GAW (128 * RSTR)
#define GEMM_SMEM_BYTES (4 * GAW * 4)   // A0 A1 B0 B1

__device__ __forceinline__ void gemm_body(const float* __restrict__ X,
                                          const float* __restrict__ W,
                                          const float* __restrict__ bias,
                                          float* __restrict__ Y,
                                          int M, int N, int K,
                                          uint32_t* sm)
{
    const int bm = blockIdx.y * 128;
    const int bn = blockIdx.x * 128;
    const int tid = threadIdx.x;
    const int lane = tid & 31;
    const int w = tid >> 5;
    const int g = lane >> 2;
    const int tig = lane & 3;
    const int wm = (w & 1) * 64;
    const int wn = (w >> 1) * 32;

    const int lr = tid >> 1;
    const int lh = tid & 1;

    const float* Xp = X + (size_t)(bm + lr) * K + lh * 8;
    const float* Wp = W + (size_t)(bn + lr) * K + lh * 8;
    const int soff = lr * RSTR + 20 * lh;

    float acc[4][4][4];
#pragma unroll
    for (int i = 0; i < 4; i++)
#pragma unroll
        for (int j = 0; j < 4; j++)
#pragma unroll
            for (int q = 0; q < 4; q++) acc[i][j][q] = 0.f;

    const int nstage = K / 16;
    float4 xa0, xa1, wb0, wb1;

#define G_LOAD(k0) do { \
        xa0 = *(const float4*)(Xp + (k0));     xa1 = *(const float4*)(Xp + (k0) + 4); \
        wb0 = *(const float4*)(Wp + (k0));     wb1 = *(const float4*)(Wp + (k0) + 4); \
    } while (0)

#define G_STORE(buf) do { \
        uint32_t* a  = sm + (buf) * GAW + soff; \
        uint32_t* bq = sm + (2 + (buf)) * GAW + soff; \
        *(uint4*)(a)      = make_uint4(f2tf(xa0.x), f2tf(xa1.x), f2tf(xa0.y), f2tf(xa1.y)); \
        *(uint4*)(a + 4)  = make_uint4(f2tf(xa0.z), f2tf(xa1.z), f2tf(xa0.w), f2tf(xa1.w)); \
        *(uint4*)(bq)     = make_uint4(f2tf(wb0.x), f2tf(wb1.x), f2tf(wb0.y), f2tf(wb1.y)); \
        *(uint4*)(bq + 4) = make_uint4(f2tf(wb0.z), f2tf(wb1.z), f2tf(wb0.w), f2tf(wb1.w)); \
    } while (0)

    G_LOAD(0);
    G_STORE(0);
    __syncthreads();

    for (int s = 0; s < nstage; s++) {
        const int p = s & 1;
        if (s + 1 < nstage) G_LOAD((s + 1) * 16);

        const uint32_t* A = sm + p * GAW;
        const uint32_t* B = sm + (2 + p) * GAW;
#pragma unroll
        for (int gi = 0; gi < 2; gi++) {
            const int goff = 20 * gi;
            uint32_t af[4][4];
#pragma unroll
            for (int mf = 0; mf < 4; mf++) {
                int mb = wm + mf * 16;
                uint2 v1 = *(const uint2*)&A[(mb + g) * RSTR + goff + 2 * tig];
                uint2 v2 = *(const uint2*)&A[(mb + 8 + g) * RSTR + goff + 2 * tig];
                af[mf][0] = v1.x; af[mf][1] = v2.x; af[mf][2] = v1.y; af[mf][3] = v2.y;
            }
            uint2 bf[4];
#pragma unroll
            for (int nf = 0; nf < 4; nf++)
                bf[nf] = *(const uint2*)&B[(wn + nf * 8 + g) * RSTR + goff + 2 * tig];
#pragma unroll
            for (int mf = 0; mf < 4; mf++)
#pragma unroll
                for (int nf = 0; nf < 4; nf++)
                    mma_tf32(acc[mf][nf], af[mf], bf[nf].x, bf[nf].y);
        }

        if (s + 1 < nstage) {
            G_STORE(1 - p);
            __syncthreads();
        }
    }

#pragma unroll
    for (int mf = 0; mf < 4; mf++) {
        int r0 = bm + wm + mf * 16 + g;
#pragma unroll
        for (int nf = 0; nf < 4; nf++) {
            int c0 = bn + wn + nf * 8 + 2 * tig;
            float b0 = bias ? bias[c0] : 0.f;
            float b1 = bias ? bias[c0 + 1] : 0.f;
            *(float2*)&Y[(size_t)r0 * N + c0]       = make_float2(acc[mf][nf][0] + b0, acc[mf][nf][1] + b1);
            *(float2*)&Y[(size_t)(r0 + 8) * N + c0] = make_float2(acc[mf][nf][2] + b0, acc[mf][nf][3] + b1);
        }
    }
}

__global__ __launch_bounds__(256, 2)
void gemm_tf32(const float* __restrict__ X,
               const float* __restrict__ W,
               const float* __restrict__ bias,
               float* __restrict__ Y,
               int M, int N, int K)
{
    extern __shared__ uint32_t sm[];
    gemm_body(X, W, bias, Y, M, N, K, sm);
}

// fused k+v projection: blockIdx.z selects operand set (doubles resident CTAs)
__global__ __launch_bounds__(256, 2)
void gemm_tf32_kv(const float* __restrict__ Xk, const float* __restrict__ Wk, float* __restrict__ Yk,
                  const float* __restrict__ Xv, const float* __restrict__ Wv, float* __restrict__ Yv,
                  int M, int N, int K)
{
    extern __shared__ uint32_t sm[];
    if (blockIdx.z == 0) gemm_body(Xk, Wk, nullptr, Yk, M, N, K, sm);
    else                 gemm_body(Xv, Wv, nullptr, Yv, M, N, K, sm);
}

// ---------------- tf32 flash attention (R14 + Q fragments hoisted to registers) ----------------
// CTA: 128 q-rows x 64 kv-tile, 4 warps. Identical smem layouts to R12/R14;
// sP aliases the sQ buffer (sQ is dead after the one-time qf extraction).
#define SQ_STR 68
#define SV_STR 72
#define AQ_W   (128 * SQ_STR)
#define AK_W   (64 * SQ_STR)
#define AV_W   (64 * SV_STR)
#define ATTN_SMEM_BYTES ((AQ_W + AK_W + AV_W) * 4)
#define NKVT 13

__global__ __launch_bounds__(128, 2)
void attn_tf32(const float* __restrict__ Q,
               const float* __restrict__ K,
               const float* __restrict__ V,
               float* __restrict__ O)
{
    extern __shared__ uint32_t smem_u[];
    uint32_t* sQ = smem_u;            // staged Q; becomes sP after qf extraction
    uint32_t* sK = sQ + AQ_W;
    uint32_t* sV = sK + AK_W;
    uint32_t* sP = sQ;                // alias (sQ dead after hoist)

    const int b = blockIdx.z, h = blockIdx.y;
    const int m0 = blockIdx.x * 128;
    const int tid = threadIdx.x;
    const int lane = tid & 31;
    const int w = tid >> 5;
    const int g = lane >> 2;
    const int tig = lane & 3;
    const int wrow = w * 32;

    const float* Qb = Q + (size_t)b * LQ * DIMC + h * HD;
    for (int i = tid; i < 128 * 16; i += 128) {
        int r = i >> 4, c4 = (i & 15) * 4;
        float4 qv = make_float4(0.f, 0.f, 0.f, 0.f);
        if (m0 + r < LQ)
            qv = *(const float4*)(Qb + (size_t)(m0 + r) * DIMC + c4);
        uint32_t* dst = &sQ[r * SQ_STR + c4];
        dst[0] = f2tf(qv.x); dst[1] = f2tf(qv.y); dst[2] = f2tf(qv.z); dst[3] = f2tf(qv.w);
    }

    float m2[2][2], lsum[2][2];
#pragma unroll
    for (int mt = 0; mt < 2; mt++) { m2[mt][0] = -1e30f; m2[mt][1] = -1e30f; lsum[mt][0] = 0.f; lsum[mt][1] = 0.f; }
    float oacc[2][8][4];
#pragma unroll
    for (int mt = 0; mt < 2; mt++)
#pragma unroll
        for (int i = 0; i < 8; i++)
#pragma unroll
            for (int j = 0; j < 4; j++) oacc[mt][i][j] = 0.f;

    const float c1 = SCALE * 1.4426950408889634f;
    const float* Kbh = K + (size_t)b * LKV * DIMC + h * HD;
    const float* Vbh = V + (size_t)b * LKV * DIMC + h * HD;

    // register-held next K/V tile
    float4 kreg[8], vreg[8];
    const int lrr = tid >> 4;            // base row 0..7
    const int lc4 = (tid & 15) * 4;      // col 0..60

#define KV_LDG(t) do { \
        int _n0 = (t) * 64; \
        _Pragma("unroll") \
        for (int it = 0; it < 8; it++) { \
            int r = lrr + 8 * it; \
            if (_n0 + r < LKV) { \
                kreg[it] = *(const float4*)(Kbh + (size_t)(_n0 + r) * DIMC + lc4); \
                vreg[it] = *(const float4*)(Vbh + (size_t)(_n0 + r) * DIMC + lc4); \
            } else { \
                kreg[it] = make_float4(0.f, 0.f, 0.f, 0.f); \
                vreg[it] = kreg[it]; \
            } \
        } \
    } while (0)

    KV_LDG(0);
    __syncthreads();   // Q staged

    // ---- hoist Q fragments into registers (loop-invariant; frees sQ for sP) ----
    uint32_t qf[8][2][4];
#pragma unroll
    for (int kg = 0; kg < 8; kg++) {
        int kk = kg * 8;
#pragma unroll
        for (int mt = 0; mt < 2; mt++) {
            int rb = wrow + mt * 16;
            qf[kg][mt][0] = sQ[(rb + g) * SQ_STR + kk + tig];
            qf[kg][mt][1] = sQ[(rb + 8 + g) * SQ_STR + kk + tig];
            qf[kg][mt][2] = sQ[(rb + g) * SQ_STR + kk + tig + 4];
            qf[kg][mt][3] = sQ[(rb + 8 + g) * SQ_STR + kk + tig + 4];
        }
    }
    __syncthreads();   // all warps done reading sQ before it becomes sP

    for (int t = 0; t < NKVT; t++) {
        const int n0 = t * 64;
        const int nv = (LKV - n0 < 64) ? (LKV - n0) : 64;

        // ---- STS K/V from registers ----
#pragma unroll
        for (int it = 0; it < 8; it++) {
            int r = lrr + 8 * it;
            uint32_t* dk = &sK[r * SQ_STR + lc4];
            dk[0] = f2tf(kreg[it].x); dk[1] = f2tf(kreg[it].y); dk[2] = f2tf(kreg[it].z); dk[3] = f2tf(kreg[it].w);
            uint32_t* dv = &sV[r * SV_STR + lc4];
            dv[0] = f2tf(vreg[it].x); dv[1] = f2tf(vreg[it].y); dv[2] = f2tf(vreg[it].z); dv[3] = f2tf(vreg[it].w);
        }
        __syncthreads();

        // ---- S = Q @ K^T (A operand from registers) ----
        float sacc[2][8][4];
#pragma unroll
        for (int mt = 0; mt < 2; mt++)
#pragma unroll
            for (int i = 0; i < 8; i++)
#pragma unroll
                for (int j = 0; j < 4; j++) sacc[mt][i][j] = 0.f;

#pragma unroll
        for (int kg = 0; kg < 8; kg++) {
            int kk = kg * 8;
#pragma unroll
            for (int nf = 0; nf < 8; nf++) {
                uint32_t b0 = sK[(nf * 8 + g) * SQ_STR + kk + tig];
                uint32_t b1 = sK[(nf * 8 + g) * SQ_STR + kk + tig + 4];
                mma_tf32(sacc[0][nf], qf[kg][0], b0, b1);
                mma_tf32(sacc[1][nf], qf[kg][1], b0, b1);
            }
        }

        // ---- online softmax ----
#pragma unroll
        for (int mt = 0; mt < 2; mt++) {
            float mtv[2] = {-1e30f, -1e30f};
#pragma unroll
            for (int nf = 0; nf < 8; nf++) {
#pragma unroll
                for (int c = 0; c < 4; c++) {
                    int col = nf * 8 + 2 * tig + (c & 1);
                    float lg = (col < nv) ? sacc[mt][nf][c] * c1 : -1e30f;
                    sacc[mt][nf][c] = lg;
                    mtv[c >> 1] = fmaxf(mtv[c >> 1], lg);
                }
            }
#pragma unroll
            for (int rr = 0; rr < 2; rr++) {
                mtv[rr] = fmaxf(mtv[rr], __shfl_xor_sync(0xffffffffu, mtv[rr], 1));
                mtv[rr] = fmaxf(mtv[rr], __shfl_xor_sync(0xffffffffu, mtv[rr], 2));
            }
            float corr[2];
#pragma unroll
            for (int rr = 0; rr < 2; rr++) {
                float mn = fmaxf(m2[mt][rr], mtv[rr]);
                corr[rr] = exp2f(m2[mt][rr] - mn);
                m2[mt][rr] = mn;
            }
            float rsum[2] = {0.f, 0.f};
#pragma unroll
            for (int nf = 0; nf < 8; nf++) {
#pragma unroll
                for (int c = 0; c < 4; c++) {
                    int rr = c >> 1;
                    float p = exp2f(sacc[mt][nf][c] - m2[mt][rr]);
                    sacc[mt][nf][c] = p;
                    rsum[rr] += p;
                }
            }
#pragma unroll
            for (int rr = 0; rr < 2; rr++) {
                rsum[rr] += __shfl_xor_sync(0xffffffffu, rsum[rr], 1);
                rsum[rr] += __shfl_xor_sync(0xffffffffu, rsum[rr], 2);
                lsum[mt][rr] = lsum[mt][rr] * corr[rr] + rsum[rr];
            }
#pragma unroll
            for (int nf = 0; nf < 8; nf++) {
                oacc[mt][nf][0] *= corr[0];
                oacc[mt][nf][1] *= corr[0];
                oacc[mt][nf][2] *= corr[1];
                oacc[mt][nf][3] *= corr[1];
            }
            int rb0 = (wrow + mt * 16 + g) * SQ_STR;
            int rb1 = (wrow + mt * 16 + 8 + g) * SQ_STR;
#pragma unroll
            for (int nf = 0; nf < 8; nf++) {
                int cb = nf * 8 + 2 * tig;
                sP[rb0 + cb]     = f2tf(sacc[mt][nf][0]);
                sP[rb0 + cb + 1] = f2tf(sacc[mt][nf][1]);
                sP[rb1 + cb]     = f2tf(sacc[mt][nf][2]);
                sP[rb1 + cb + 1] = f2tf(sacc[mt][nf][3]);
            }
        }
        __syncwarp();

        // ---- issue next tile's K/V loads (latency covered by PV mma) ----
        if (t + 1 < NKVT) KV_LDG(t + 1);

        // ---- O += P @ V ----
#pragma unroll
        for (int kk = 0; kk < 64; kk += 8) {
            uint32_t ap[2][4];
#pragma unroll
            for (int mt = 0; mt < 2; mt++) {
                int rb = wrow + mt * 16;
                ap[mt][0] = sP[(rb + g) * SQ_STR + kk + tig];
                ap[mt][1] = sP[(rb + 8 + g) * SQ_STR + kk + tig];
                ap[mt][2] = sP[(rb + g) * SQ_STR + kk + tig + 4];
                ap[mt][3] = sP[(rb + 8 + g) * SQ_STR + kk + tig + 4];
            }
#pragma unroll
            for (int nf = 0; nf < 8; nf++) {
                uint32_t b0 = sV[(kk + tig) * SV_STR + nf * 8 + g];
                uint32_t b1 = sV[(kk + tig + 4) * SV_STR + nf * 8 + g];
                mma_tf32(oacc[0][nf], ap[0], b0, b1);
                mma_tf32(oacc[1][nf], ap[1], b0, b1);
            }
        }
        __syncthreads();
    }

    // epilogue
    float* Ob = O + (size_t)b * LQ * DIMC + h * HD;
#pragma unroll
    for (int mt = 0; mt < 2; mt++) {
        float inv0 = 1.f / lsum[mt][0];
        float inv1 = 1.f / lsum[mt][1];
        int r0 = m0 + wrow + mt * 16 + g;
        int r1 = r0 + 8;
#pragma unroll
        for (int nf = 0; nf < 8; nf++) {
            int cb = nf * 8 + 2 * tig;
            if (r0 < LQ)
                *(float2*)&Ob[(size_t)r0 * DIMC + cb] =
                    make_float2(oacc[mt][nf][0] * inv0, oacc[mt][nf][1] * inv0);
            if (r1 < LQ)
                *(float2*)&Ob[(size_t)r1 * DIMC + cb] =
                    make_float2(oacc[mt][nf][2] * inv1, oacc[mt][nf][3] * inv1);
        }
    }
}

// ---------------- launch ----------------
extern "C" void kernel_launch(void* const* d_in, const int* in_sizes, int n_in,
                              void* d_out, int out_size)
{
    const float* x      = (const float*)d_in[0];
    const float* conv_q = (const float*)d_in[3];
    const float* bnq_s  = (const float*)d_in[4];
    const float* bnq_b  = (const float*)d_in[5];
    const float* bnq_m  = (const float*)d_in[6];
    const float* bnq_v  = (const float*)d_in[7];
    const float* conv_k = (const float*)d_in[8];
    const float* bnk_s  = (const float*)d_in[9];
    const float* bnk_b  = (const float*)d_in[10];
    const float* bnk_m  = (const float*)d_in[11];
    const float* bnk_v  = (const float*)d_in[12];
    const float* conv_v = (const float*)d_in[13];
    const float* bnv_s  = (const float*)d_in[14];
    const float* bnv_b  = (const float*)d_in[15];
    const float* bnv_m  = (const float*)d_in[16];
    const float* bnv_v  = (const float*)d_in[17];
    const float* wq     = (const float*)d_in[18];
    const float* wk     = (const float*)d_in[19];
    const float* wv     = (const float*)d_in[20];
    const float* w_last = (const float*)d_in[21];
    const float* b_last = (const float*)d_in[22];

    float *qc, *kc, *vc, *qp, *kp, *vp, *ob;
    cudaGetSymbolAddress((void**)&qc, g_qc);
    cudaGetSymbolAddress((void**)&kc, g_kc);
    cudaGetSymbolAddress((void**)&vc, g_vc);
    cudaGetSymbolAddress((void**)&qp, g_qp);
    cudaGetSymbolAddress((void**)&kp, g_kp);
    cudaGetSymbolAddress((void**)&vp, g_vp);
    cudaGetSymbolAddress((void**)&ob, g_ob);

    cudaFuncSetAttribute(gemm_tf32, cudaFuncAttributeMaxDynamicSharedMemorySize, GEMM_SMEM_BYTES);
    cudaFuncSetAttribute(gemm_tf32_kv, cudaFuncAttributeMaxDynamicSharedMemorySize, GEMM_SMEM_BYTES);
    cudaFuncSetAttribute(attn_tf32, cudaFuncAttributeMaxDynamicSharedMemorySize, ATTN_SMEM_BYTES);

    // depthwise conv + BN (float4 channel vectorization)
    {
        int totq = BATCH * LQ * (DIMC / 4);
        int totk = BATCH * LKV * (DIMC / 4);
        dwconv_bn_v4_kernel<<<(totq + 255) / 256, 256>>>(x, conv_q, bnq_s, bnq_b, bnq_m, bnq_v, qc);
        dwconv_bn_kv_v4_kernel<<<(totk + 255) / 256, 256>>>(x,
            conv_k, bnk_s, bnk_b, bnk_m, bnk_v,
            conv_v, bnv_s, bnv_b, bnv_m, bnv_v, kc, vc);
    }

    // projections: q alone; k+v fused into one launch (grid z)
    gemm_tf32<<<dim3(DIMC / 128, (BATCH * LQ) / 128), 256, GEMM_SMEM_BYTES>>>(qc, wq, nullptr, qp, BATCH * LQ, DIMC, DIMC);
    gemm_tf32_kv<<<dim3(DIMC / 128, (BATCH * LKV) / 128, 2), 256, GEMM_SMEM_BYTES>>>(
        kc, wk, kp, vc, wv, vp, BATCH * LKV, DIMC, DIMC);

    // attention: 128 q-rows per CTA
    attn_tf32<<<dim3((LQ + 127) / 128, HEADS, BATCH), 128, ATTN_SMEM_BYTES>>>(qp, kp, vp, ob);

    // final projection + bias -> d_out
    gemm_tf32<<<dim3(DIMC / 128, (BATCH * LQ) / 128), 256, GEMM_SMEM_BYTES>>>(ob, w_last, b_last, (float*)d_out,
                                                                              BATCH * LQ, DIMC, DIMC);
}

// round 16
// speedup vs baseline: 1.1586x; 1.1586x over previous
#include <cuda_runtime.h>
#include <math.h>
#include <stdint.h>

#define BATCH 8
#define DIMC 384
#define HEADS 6
#define HD 64
#define HIN 56
#define LQ 3136        // 56*56
#define LKV 784        // 28*28
#define EPS 1e-5f
#define SCALE 0.05103103630798288f   // 384^-0.5

// ---------------- scratch ----------------
__device__ float g_qc[BATCH * LQ  * DIMC];
__device__ float g_kc[BATCH * LKV * DIMC];
__device__ float g_vc[BATCH * LKV * DIMC];
__device__ float g_qp[BATCH * LQ  * DIMC];
__device__ float g_kp[BATCH * LKV * DIMC];
__device__ float g_vp[BATCH * LKV * DIMC];
__device__ float g_ob[BATCH * LQ  * DIMC];

// ---------------- tf32 helpers ----------------
__device__ __forceinline__ uint32_t f2tf(float f) {
    uint32_t u;
    asm("cvt.rna.tf32.f32 %0, %1;" : "=r"(u) : "f"(f));
    return u;
}

__device__ __forceinline__ void mma_tf32(float c[4], const uint32_t a[4], uint32_t b0, uint32_t b1) {
    asm volatile(
        "mma.sync.aligned.m16n8k8.row.col.f32.tf32.tf32.f32 "
        "{%0,%1,%2,%3}, {%4,%5,%6,%7}, {%8,%9}, {%0,%1,%2,%3};\n"
        : "+f"(c[0]), "+f"(c[1]), "+f"(c[2]), "+f"(c[3])
        : "r"(a[0]), "r"(a[1]), "r"(a[2]), "r"(a[3]), "r"(b0), "r"(b1));
}

// ---------------- depthwise 3x3 conv + BN (q path, stride 1) — R14 ----------------
__global__ void dwconv_bn_kernel(const float* __restrict__ x,
                                 const float* __restrict__ wt,
                                 const float* __restrict__ sc,
                                 const float* __restrict__ bb,
                                 const float* __restrict__ mn,
                                 const float* __restrict__ vr,
                                 float* __restrict__ out,
                                 int stride, int Hout)
{
    int idx = blockIdx.x * blockDim.x + threadIdx.x;
    int total = BATCH * Hout * Hout * DIMC;
    if (idx >= total) return;
    int c = idx % DIMC;
    int t = (idx / DIMC) % (Hout * Hout);
    int b = idx / (DIMC * Hout * Hout);
    int oy = t / Hout, ox = t % Hout;

    float acc = 0.f;
#pragma unroll
    for (int dy = 0; dy < 3; dy++) {
        int iy = oy * stride + dy - 1;
        if (iy < 0 || iy >= HIN) continue;
#pragma unroll
        for (int dx = 0; dx < 3; dx++) {
            int ix = ox * stride + dx - 1;
            if (ix < 0 || ix >= HIN) continue;
            acc += x[((size_t)b * LQ + iy * HIN + ix) * DIMC + c] * wt[c * 9 + dy * 3 + dx];
        }
    }
    float inv = rsqrtf(vr[c] + EPS);
    out[idx] = (acc - mn[c]) * inv * sc[c] + bb[c];
}

// ---------------- fused k+v depthwise conv + BN (stride 2) — R14 ----------------
__global__ void dwconv_bn_kv_kernel(const float* __restrict__ x,
                                    const float* __restrict__ wtk,
                                    const float* __restrict__ sck,
                                    const float* __restrict__ bbk,
                                    const float* __restrict__ mnk,
                                    const float* __restrict__ vrk,
                                    const float* __restrict__ wtv,
                                    const float* __restrict__ scv,
                                    const float* __restrict__ bbv,
                                    const float* __restrict__ mnv,
                                    const float* __restrict__ vrv,
                                    float* __restrict__ outk,
                                    float* __restrict__ outv)
{
    int idx = blockIdx.x * blockDim.x + threadIdx.x;
    int total = BATCH * 28 * 28 * DIMC;
    if (idx >= total) return;
    int c = idx % DIMC;
    int t = (idx / DIMC) % (28 * 28);
    int b = idx / (DIMC * 28 * 28);
    int oy = t / 28, ox = t % 28;

    float acck = 0.f, accv = 0.f;
#pragma unroll
    for (int dy = 0; dy < 3; dy++) {
        int iy = oy * 2 + dy - 1;
        if (iy < 0 || iy >= HIN) continue;
#pragma unroll
        for (int dx = 0; dx < 3; dx++) {
            int ix = ox * 2 + dx - 1;
            if (ix < 0 || ix >= HIN) continue;
            float xv = x[((size_t)b * LQ + iy * HIN + ix) * DIMC + c];
            acck += xv * wtk[c * 9 + dy * 3 + dx];
            accv += xv * wtv[c * 9 + dy * 3 + dx];
        }
    }
    float invk = rsqrtf(vrk[c] + EPS);
    float invv = rsqrtf(vrv[c] + EPS);
    outk[idx] = (acck - mnk[c]) * invk * sck[c] + bbk[c];
    outv[idx] = (accv - mnv[c]) * invv * scv[c] + bbv[c];
}

// ---------------- tf32 GEMM body (R11/R12 proven): Y = X @ W^T (+bias) ----------------
#define RSTR 40
#define GAW (128 * RSTR)
#define GEMM_SMEM_BYTES (4 * GAW * 4)   // A0 A1 B0 B1

__device__ __forceinline__ void gemm_body(const float* __restrict__ X,
                                          const float* __restrict__ W,
                                          const float* __restrict__ bias,
                                          float* __restrict__ Y,
                                          int M, int N, int K,
                                          uint32_t* sm)
{
    const int bm = blockIdx.y * 128;
    const int bn = blockIdx.x * 128;
    const int tid = threadIdx.x;
    const int lane = tid & 31;
    const int w = tid >> 5;
    const int g = lane >> 2;
    const int tig = lane & 3;
    const int wm = (w & 1) * 64;
    const int wn = (w >> 1) * 32;

    const int lr = tid >> 1;
    const int lh = tid & 1;

    const float* Xp = X + (size_t)(bm + lr) * K + lh * 8;
    const float* Wp = W + (size_t)(bn + lr) * K + lh * 8;
    const int soff = lr * RSTR + 20 * lh;

    float acc[4][4][4];
#pragma unroll
    for (int i = 0; i < 4; i++)
#pragma unroll
        for (int j = 0; j < 4; j++)
#pragma unroll
            for (int q = 0; q < 4; q++) acc[i][j][q] = 0.f;

    const int nstage = K / 16;
    float4 xa0, xa1, wb0, wb1;

#define G_LOAD(k0) do { \
        xa0 = *(const float4*)(Xp + (k0));     xa1 = *(const float4*)(Xp + (k0) + 4); \
        wb0 = *(const float4*)(Wp + (k0));     wb1 = *(const float4*)(Wp + (k0) + 4); \
    } while (0)

#define G_STORE(buf) do { \
        uint32_t* a  = sm + (buf) * GAW + soff; \
        uint32_t* bq = sm + (2 + (buf)) * GAW + soff; \
        *(uint4*)(a)      = make_uint4(f2tf(xa0.x), f2tf(xa1.x), f2tf(xa0.y), f2tf(xa1.y)); \
        *(uint4*)(a + 4)  = make_uint4(f2tf(xa0.z), f2tf(xa1.z), f2tf(xa0.w), f2tf(xa1.w)); \
        *(uint4*)(bq)     = make_uint4(f2tf(wb0.x), f2tf(wb1.x), f2tf(wb0.y), f2tf(wb1.y)); \
        *(uint4*)(bq + 4) = make_uint4(f2tf(wb0.z), f2tf(wb1.z), f2tf(wb0.w), f2tf(wb1.w)); \
    } while (0)

    G_LOAD(0);
    G_STORE(0);
    __syncthreads();

    for (int s = 0; s < nstage; s++) {
        const int p = s & 1;
        if (s + 1 < nstage) G_LOAD((s + 1) * 16);

        const uint32_t* A = sm + p * GAW;
        const uint32_t* B = sm + (2 + p) * GAW;
#pragma unroll
        for (int gi = 0; gi < 2; gi++) {
            const int goff = 20 * gi;
            uint32_t af[4][4];
#pragma unroll
            for (int mf = 0; mf < 4; mf++) {
                int mb = wm + mf * 16;
                uint2 v1 = *(const uint2*)&A[(mb + g) * RSTR + goff + 2 * tig];
                uint2 v2 = *(const uint2*)&A[(mb + 8 + g) * RSTR + goff + 2 * tig];
                af[mf][0] = v1.x; af[mf][1] = v2.x; af[mf][2] = v1.y; af[mf][3] = v2.y;
            }
            uint2 bf[4];
#pragma unroll
            for (int nf = 0; nf < 4; nf++)
                bf[nf] = *(const uint2*)&B[(wn + nf * 8 + g) * RSTR + goff + 2 * tig];
#pragma unroll
            for (int mf = 0; mf < 4; mf++)
#pragma unroll
                for (int nf = 0; nf < 4; nf++)
                    mma_tf32(acc[mf][nf], af[mf], bf[nf].x, bf[nf].y);
        }

        if (s + 1 < nstage) {
            G_STORE(1 - p);
            __syncthreads();
        }
    }

#pragma unroll
    for (int mf = 0; mf < 4; mf++) {
        int r0 = bm + wm + mf * 16 + g;
#pragma unroll
        for (int nf = 0; nf < 4; nf++) {
            int c0 = bn + wn + nf * 8 + 2 * tig;
            float b0 = bias ? bias[c0] : 0.f;
            float b1 = bias ? bias[c0 + 1] : 0.f;
            *(float2*)&Y[(size_t)r0 * N + c0]       = make_float2(acc[mf][nf][0] + b0, acc[mf][nf][1] + b1);
            *(float2*)&Y[(size_t)(r0 + 8) * N + c0] = make_float2(acc[mf][nf][2] + b0, acc[mf][nf][3] + b1);
        }
    }
}

__global__ __launch_bounds__(256, 2)
void gemm_tf32(const float* __restrict__ X,
               const float* __restrict__ W,
               const float* __restrict__ bias,
               float* __restrict__ Y,
               int M, int N, int K)
{
    extern __shared__ uint32_t sm[];
    gemm_body(X, W, bias, Y, M, N, K, sm);
}

// fused k+v projection: blockIdx.z selects operand set (R15 measured win: 35.5us)
__global__ __launch_bounds__(256, 2)
void gemm_tf32_kv(const float* __restrict__ Xk, const float* __restrict__ Wk, float* __restrict__ Yk,
                  const float* __restrict__ Xv, const float* __restrict__ Wv, float* __restrict__ Yv,
                  int M, int N, int K)
{
    extern __shared__ uint32_t sm[];
    if (blockIdx.z == 0) gemm_body(Xk, Wk, nullptr, Yk, M, N, K, sm);
    else                 gemm_body(Xv, Wv, nullptr, Yv, M, N, K, sm);
}

// ---------------- tf32 flash attention (R14 verbatim, measured ~290us) ----------------
// CTA: 128 q-rows x 64 kv-tile, 4 warps; warp owns 32 q-rows (2 m-tiles of 16).
// Register-pipelined K/V global loads; R12 smem layouts.
#define SQ_STR 68
#define SV_STR 72
#define AQ_W   (128 * SQ_STR)
#define AK_W   (64 * SQ_STR)
#define AV_W   (64 * SV_STR)
#define AP_W   (128 * SQ_STR)
#define ATTN_SMEM_BYTES ((AQ_W + AK_W + AV_W + AP_W) * 4)
#define NKVT 13

__global__ __launch_bounds__(128, 2)
void attn_tf32(const float* __restrict__ Q,
               const float* __restrict__ K,
               const float* __restrict__ V,
               float* __restrict__ O)
{
    extern __shared__ uint32_t smem_u[];
    uint32_t* sQ = smem_u;
    uint32_t* sK = sQ + AQ_W;
    uint32_t* sV = sK + AK_W;
    uint32_t* sP = sV + AV_W;

    const int b = blockIdx.z, h = blockIdx.y;
    const int m0 = blockIdx.x * 128;
    const int tid = threadIdx.x;
    const int lane = tid & 31;
    const int w = tid >> 5;
    const int g = lane >> 2;
    const int tig = lane & 3;
    const int wrow = w * 32;

    const float* Qb = Q + (size_t)b * LQ * DIMC + h * HD;
    for (int i = tid; i < 128 * 16; i += 128) {
        int r = i >> 4, c4 = (i & 15) * 4;
        float4 qv = make_float4(0.f, 0.f, 0.f, 0.f);
        if (m0 + r < LQ)
            qv = *(const float4*)(Qb + (size_t)(m0 + r) * DIMC + c4);
        uint32_t* dst = &sQ[r * SQ_STR + c4];
        dst[0] = f2tf(qv.x); dst[1] = f2tf(qv.y); dst[2] = f2tf(qv.z); dst[3] = f2tf(qv.w);
    }

    float m2[2][2], lsum[2][2];
#pragma unroll
    for (int mt = 0; mt < 2; mt++) { m2[mt][0] = -1e30f; m2[mt][1] = -1e30f; lsum[mt][0] = 0.f; lsum[mt][1] = 0.f; }
    float oacc[2][8][4];
#pragma unroll
    for (int mt = 0; mt < 2; mt++)
#pragma unroll
        for (int i = 0; i < 8; i++)
#pragma unroll
            for (int j = 0; j < 4; j++) oacc[mt][i][j] = 0.f;

    const float c1 = SCALE * 1.4426950408889634f;
    const float* Kbh = K + (size_t)b * LKV * DIMC + h * HD;
    const float* Vbh = V + (size_t)b * LKV * DIMC + h * HD;

    float4 kreg[8], vreg[8];
    const int lrr = tid >> 4;            // base row 0..7
    const int lc4 = (tid & 15) * 4;      // col 0..60

#define KV_LDG(t) do { \
        int _n0 = (t) * 64; \
        _Pragma("unroll") \
        for (int it = 0; it < 8; it++) { \
            int r = lrr + 8 * it; \
            if (_n0 + r < LKV) { \
                kreg[it] = *(const float4*)(Kbh + (size_t)(_n0 + r) * DIMC + lc4); \
                vreg[it] = *(const float4*)(Vbh + (size_t)(_n0 + r) * DIMC + lc4); \
            } else { \
                kreg[it] = make_float4(0.f, 0.f, 0.f, 0.f); \
                vreg[it] = kreg[it]; \
            } \
        } \
    } while (0)

    KV_LDG(0);
    __syncthreads();   // Q staged

    for (int t = 0; t < NKVT; t++) {
        const int n0 = t * 64;
        const int nv = (LKV - n0 < 64) ? (LKV - n0) : 64;

        // ---- STS K/V from registers ----
#pragma unroll
        for (int it = 0; it < 8; it++) {
            int r = lrr + 8 * it;
            uint32_t* dk = &sK[r * SQ_STR + lc4];
            dk[0] = f2tf(kreg[it].x); dk[1] = f2tf(kreg[it].y); dk[2] = f2tf(kreg[it].z); dk[3] = f2tf(kreg[it].w);
            uint32_t* dv = &sV[r * SV_STR + lc4];
            dv[0] = f2tf(vreg[it].x); dv[1] = f2tf(vreg[it].y); dv[2] = f2tf(vreg[it].z); dv[3] = f2tf(vreg[it].w);
        }
        __syncthreads();

        // ---- S = Q @ K^T ----
        float sacc[2][8][4];
#pragma unroll
        for (int mt = 0; mt < 2; mt++)
#pragma unroll
            for (int i = 0; i < 8; i++)
#pragma unroll
                for (int j = 0; j < 4; j++) sacc[mt][i][j] = 0.f;

#pragma unroll
        for (int kk = 0; kk < 64; kk += 8) {
            uint32_t aq[2][4];
#pragma unroll
            for (int mt = 0; mt < 2; mt++) {
                int rb = wrow + mt * 16;
                aq[mt][0] = sQ[(rb + g) * SQ_STR + kk + tig];
                aq[mt][1] = sQ[(rb + 8 + g) * SQ_STR + kk + tig];
                aq[mt][2] = sQ[(rb + g) * SQ_STR + kk + tig + 4];
                aq[mt][3] = sQ[(rb + 8 + g) * SQ_STR + kk + tig + 4];
            }
#pragma unroll
            for (int nf = 0; nf < 8; nf++) {
                uint32_t b0 = sK[(nf * 8 + g) * SQ_STR + kk + tig];
                uint32_t b1 = sK[(nf * 8 + g) * SQ_STR + kk + tig + 4];
                mma_tf32(sacc[0][nf], aq[0], b0, b1);
                mma_tf32(sacc[1][nf], aq[1], b0, b1);
            }
        }

        // ---- online softmax ----
#pragma unroll
        for (int mt = 0; mt < 2; mt++) {
            float mtv[2] = {-1e30f, -1e30f};
#pragma unroll
            for (int nf = 0; nf < 8; nf++) {
#pragma unroll
                for (int c = 0; c < 4; c++) {
                    int col = nf * 8 + 2 * tig + (c & 1);
                    float lg = (col < nv) ? sacc[mt][nf][c] * c1 : -1e30f;
                    sacc[mt][nf][c] = lg;
                    mtv[c >> 1] = fmaxf(mtv[c >> 1], lg);
                }
            }
#pragma unroll
            for (int rr = 0; rr < 2; rr++) {
                mtv[rr] = fmaxf(mtv[rr], __shfl_xor_sync(0xffffffffu, mtv[rr], 1));
                mtv[rr] = fmaxf(mtv[rr], __shfl_xor_sync(0xffffffffu, mtv[rr], 2));
            }
            float corr[2];
#pragma unroll
            for (int rr = 0; rr < 2; rr++) {
                float mn = fmaxf(m2[mt][rr], mtv[rr]);
                corr[rr] = exp2f(m2[mt][rr] - mn);
                m2[mt][rr] = mn;
            }
            float rsum[2] = {0.f, 0.f};
#pragma unroll
            for (int nf = 0; nf < 8; nf++) {
#pragma unroll
                for (int c = 0; c < 4; c++) {
                    int rr = c >> 1;
                    float p = exp2f(sacc[mt][nf][c] - m2[mt][rr]);
                    sacc[mt][nf][c] = p;
                    rsum[rr] += p;
                }
            }
#pragma unroll
            for (int rr = 0; rr < 2; rr++) {
                rsum[rr] += __shfl_xor_sync(0xffffffffu, rsum[rr], 1);
                rsum[rr] += __shfl_xor_sync(0xffffffffu, rsum[rr], 2);
                lsum[mt][rr] = lsum[mt][rr] * corr[rr] + rsum[rr];
            }
#pragma unroll
            for (int nf = 0; nf < 8; nf++) {
                oacc[mt][nf][0] *= corr[0];
                oacc[mt][nf][1] *= corr[0];
                oacc[mt][nf][2] *= corr[1];
                oacc[mt][nf][3] *= corr[1];
            }
            int rb0 = (wrow + mt * 16 + g) * SQ_STR;
            int rb1 = (wrow + mt * 16 + 8 + g) * SQ_STR;
#pragma unroll
            for (int nf = 0; nf < 8; nf++) {
                int cb = nf * 8 + 2 * tig;
                sP[rb0 + cb]     = f2tf(sacc[mt][nf][0]);
                sP[rb0 + cb + 1] = f2tf(sacc[mt][nf][1]);
                sP[rb1 + cb]     = f2tf(sacc[mt][nf][2]);
                sP[rb1 + cb + 1] = f2tf(sacc[mt][nf][3]);
            }
        }
        __syncwarp();

        // ---- issue next tile's K/V loads (latency covered by PV mma) ----
        if (t + 1 < NKVT) KV_LDG(t + 1);

        // ---- O += P @ V ----
#pragma unroll
        for (int kk = 0; kk < 64; kk += 8) {
            uint32_t ap[2][4];
#pragma unroll
            for (int mt = 0; mt < 2; mt++) {
                int rb = wrow + mt * 16;
                ap[mt][0] = sP[(rb + g) * SQ_STR + kk + tig];
                ap[mt][1] = sP[(rb + 8 + g) * SQ_STR + kk + tig];
                ap[mt][2] = sP[(rb + g) * SQ_STR + kk + tig + 4];
                ap[mt][3] = sP[(rb + 8 + g) * SQ_STR + kk + tig + 4];
            }
#pragma unroll
            for (int nf = 0; nf < 8; nf++) {
                uint32_t b0 = sV[(kk + tig) * SV_STR + nf * 8 + g];
                uint32_t b1 = sV[(kk + tig + 4) * SV_STR + nf * 8 + g];
                mma_tf32(oacc[0][nf], ap[0], b0, b1);
                mma_tf32(oacc[1][nf], ap[1], b0, b1);
            }
        }
        __syncthreads();
    }

    // epilogue
    float* Ob = O + (size_t)b * LQ * DIMC + h * HD;
#pragma unroll
    for (int mt = 0; mt < 2; mt++) {
        float inv0 = 1.f / lsum[mt][0];
        float inv1 = 1.f / lsum[mt][1];
        int r0 = m0 + wrow + mt * 16 + g;
        int r1 = r0 + 8;
#pragma unroll
        for (int nf = 0; nf < 8; nf++) {
            int cb = nf * 8 + 2 * tig;
            if (r0 < LQ)
                *(float2*)&Ob[(size_t)r0 * DIMC + cb] =
                    make_float2(oacc[mt][nf][0] * inv0, oacc[mt][nf][1] * inv0);
            if (r1 < LQ)
                *(float2*)&Ob[(size_t)r1 * DIMC + cb] =
                    make_float2(oacc[mt][nf][2] * inv1, oacc[mt][nf][3] * inv1);
        }
    }
}

// ---------------- launch ----------------
extern "C" void kernel_launch(void* const* d_in, const int* in_sizes, int n_in,
                              void* d_out, int out_size)
{
    const float* x      = (const float*)d_in[0];
    const float* conv_q = (const float*)d_in[3];
    const float* bnq_s  = (const float*)d_in[4];
    const float* bnq_b  = (const float*)d_in[5];
    const float* bnq_m  = (const float*)d_in[6];
    const float* bnq_v  = (const float*)d_in[7];
    const float* conv_k = (const float*)d_in[8];
    const float* bnk_s  = (const float*)d_in[9];
    const float* bnk_b  = (const float*)d_in[10];
    const float* bnk_m  = (const float*)d_in[11];
    const float* bnk_v  = (const float*)d_in[12];
    const float* conv_v = (const float*)d_in[13];
    const float* bnv_s  = (const float*)d_in[14];
    const float* bnv_b  = (const float*)d_in[15];
    const float* bnv_m  = (const float*)d_in[16];
    const float* bnv_v  = (const float*)d_in[17];
    const float* wq     = (const float*)d_in[18];
    const float* wk     = (const float*)d_in[19];
    const float* wv     = (const float*)d_in[20];
    const float* w_last = (const float*)d_in[21];
    const float* b_last = (const float*)d_in[22];

    float *qc, *kc, *vc, *qp, *kp, *vp, *ob;
    cudaGetSymbolAddress((void**)&qc, g_qc);
    cudaGetSymbolAddress((void**)&kc, g_kc);
    cudaGetSymbolAddress((void**)&vc, g_vc);
    cudaGetSymbolAddress((void**)&qp, g_qp);
    cudaGetSymbolAddress((void**)&kp, g_kp);
    cudaGetSymbolAddress((void**)&vp, g_vp);
    cudaGetSymbolAddress((void**)&ob, g_ob);

    cudaFuncSetAttribute(gemm_tf32, cudaFuncAttributeMaxDynamicSharedMemorySize, GEMM_SMEM_BYTES);
    cudaFuncSetAttribute(gemm_tf32_kv, cudaFuncAttributeMaxDynamicSharedMemorySize, GEMM_SMEM_BYTES);
    cudaFuncSetAttribute(attn_tf32, cudaFuncAttributeMaxDynamicSharedMemorySize, ATTN_SMEM_BYTES);

    // depthwise conv + BN: q (stride 1) + fused k/v (stride 2) — R14 versions
    {
        int totq = BATCH * LQ * DIMC;
        int totk = BATCH * LKV * DIMC;
        dwconv_bn_kernel<<<(totq + 255) / 256, 256>>>(x, conv_q, bnq_s, bnq_b, bnq_m, bnq_v, qc, 1, 56);
        dwconv_bn_kv_kernel<<<(totk + 255) / 256, 256>>>(x,
            conv_k, bnk_s, bnk_b, bnk_m, bnk_v,
            conv_v, bnv_s, bnv_b, bnv_m, bnv_v, kc, vc);
    }

    // projections: q alone; k+v fused into one launch (grid z)
    gemm_tf32<<<dim3(DIMC / 128, (BATCH * LQ) / 128), 256, GEMM_SMEM_BYTES>>>(qc, wq, nullptr, qp, BATCH * LQ, DIMC, DIMC);
    gemm_tf32_kv<<<dim3(DIMC / 128, (BATCH * LKV) / 128, 2), 256, GEMM_SMEM_BYTES>>>(
        kc, wk, kp, vc, wv, vp, BATCH * LKV, DIMC, DIMC);

    // attention: 128 q-rows per CTA (R14 verbatim)
    attn_tf32<<<dim3((LQ + 127) / 128, HEADS, BATCH), 128, ATTN_SMEM_BYTES>>>(qp, kp, vp, ob);

    // final projection + bias -> d_out
    gemm_tf32<<<dim3(DIMC / 128, (BATCH * LQ) / 128), 256, GEMM_SMEM_BYTES>>>(ob, w_last, b_last, (float*)d_out,
                                                                              BATCH * LQ, DIMC, DIMC);
}